// round 6
// baseline (speedup 1.0000x reference)
#include <cuda_runtime.h>
#include <cstdint>

// HighOrderActivation: B=1024, G=512, K=4, D=64.
// out[b,g,:] = c0*P[g,15,:] + c1*P[g,id1,:] + c2*P[g,id2,:] + c3*P[g,id3,:]
// (i0..i3)=argsort(X[b,g,:]); c=(min, gaps); id1=15-2^i0, id2=2^i2+2^i3, id3=2^i3.
//
// R4 change: gathers go through shared memory. The R3 bottleneck was the
// L1TEX per-instruction cost of full-warp LDG.128 (~4cyc/instr, no broadcast
// dedup). The smem crossbar DOES dedup broadcasts: with rows 256B apart,
// same-chunk lanes across the warp's 4 pairs conflict only on *distinct*
// rows (avg 2.7-3.1), and the always-read row 15 is a pure broadcast.
// One g per block, 64 b per block (512 threads) amortizes the 4KB table fill.

#define BATCH   1024
#define GROUPS  512
#define B_TILE  64
#define PAIRS   (BATCH * GROUPS)

__global__ __launch_bounds__(512, 4)
void hoa_kernel(const float4* __restrict__ Xv,      // [PAIRS] float4
                const float4* __restrict__ Pv,      // [GROUPS*256] float4
                float4* __restrict__ Ov)            // [PAIRS*16] float4
{
    __shared__ float sP[16 * 64];                    // params[g]: 16 rows x 64 f32

    const int tid = threadIdx.x;
    const int g   = blockIdx.x & (GROUPS - 1);       // block-uniform group
    const int bt  = blockIdx.x >> 9;                 // b-tile index (0..15)

    // Cooperative fill: 256 float4 = 4KB, threads 0..255.
    if (tid < 256) {
        reinterpret_cast<float4*>(sP)[tid] = Pv[g * 256 + tid];
    }

    const int b = bt * B_TILE + (tid >> 3);
    const int q = tid & 7;                           // float4 chunk 0..7
    const int p = b * GROUPS + g;

    // X load overlaps the fill (independent of smem).
    const float4 x = Xv[p];

    float v0 = x.x, v1 = x.y, v2 = x.z, v3 = x.w;
    int   i0 = 0,   i1 = 1,   i2 = 2,   i3 = 3;

    #define CSWAP(a, bb, ia, ib)                        \
        { bool _sw = (a > bb);                          \
          float _lo = fminf(a, bb), _hi = fmaxf(a, bb); \
          a = _lo; bb = _hi;                            \
          int _t = ia; ia = _sw ? ib : ia; ib = _sw ? _t : ib; }
    CSWAP(v0, v1, i0, i1);
    CSWAP(v2, v3, i2, i3);
    CSWAP(v0, v2, i0, i2);
    CSWAP(v1, v3, i1, i3);
    CSWAP(v1, v2, i1, i2);
    #undef CSWAP

    const float c0 = v0;
    const float c1 = v1 - v0;
    const float c2 = v2 - v1;
    const float c3 = v3 - v2;

    const int e0 = 1 << i0;
    const int e2 = 1 << i2;
    const int e3 = 1 << i3;
    const int id1 = 15 - e0;
    const int id2 = e2 + e3;
    const int id3 = e3;

    __syncthreads();

    // Gather from smem. Row r chunk c: sP + r*64 + c*4 floats (16B aligned).
    const float* s = sP + q * 4;

    const float4 a0 = *reinterpret_cast<const float4*>(s + 15  * 64);
    const float4 b0 = *reinterpret_cast<const float4*>(s + 15  * 64 + 32);
    const float4 a1 = *reinterpret_cast<const float4*>(s + id1 * 64);
    const float4 b1 = *reinterpret_cast<const float4*>(s + id1 * 64 + 32);
    const float4 a2 = *reinterpret_cast<const float4*>(s + id2 * 64);
    const float4 b2 = *reinterpret_cast<const float4*>(s + id2 * 64 + 32);
    const float4 a3 = *reinterpret_cast<const float4*>(s + id3 * 64);
    const float4 b3 = *reinterpret_cast<const float4*>(s + id3 * 64 + 32);

    float4 oa, ob;
    oa.x = c0 * a0.x + c1 * a1.x + c2 * a2.x + c3 * a3.x;
    oa.y = c0 * a0.y + c1 * a1.y + c2 * a2.y + c3 * a3.y;
    oa.z = c0 * a0.z + c1 * a1.z + c2 * a2.z + c3 * a3.z;
    oa.w = c0 * a0.w + c1 * a1.w + c2 * a2.w + c3 * a3.w;

    ob.x = c0 * b0.x + c1 * b1.x + c2 * b2.x + c3 * b3.x;
    ob.y = c0 * b0.y + c1 * b1.y + c2 * b2.y + c3 * b3.y;
    ob.z = c0 * b0.z + c1 * b1.z + c2 * b2.z + c3 * b3.z;
    ob.w = c0 * b0.w + c1 * b1.w + c2 * b2.w + c3 * b3.w;

    float4* __restrict__ o = Ov + (size_t)p * 16 + q;
    o[0] = oa;
    o[8] = ob;
}

extern "C" void kernel_launch(void* const* d_in, const int* in_sizes, int n_in,
                              void* d_out, int out_size)
{
    const float4* Xv = (const float4*)d_in[0];   // X: [1024, 512, 4] f32
    const float4* Pv = (const float4*)d_in[1];   // params: [512, 16, 64] f32
    float4*       Ov = (float4*)d_out;           // out: [1024, 512, 64] f32

    // One block per (g, 64-b tile): 512 * 16 = 8192 blocks, 512 threads.
    const int grid = GROUPS * (BATCH / B_TILE);
    hoa_kernel<<<grid, 512>>>(Xv, Pv, Ov);
}

// round 8
// speedup vs baseline: 1.3059x; 1.3059x over previous
#include <cuda_runtime.h>
#include <cstdint>

// HighOrderActivation: B=1024, G=512, K=4, D=64.
// out[b,g,:] = c0*P[g,15,:] + c1*P[g,id1,:] + c2*P[g,id2,:] + c3*P[g,id3,:]
// (i0..i3)=argsort(X[b,g,:]); c=(min, gaps); id1=15-2^i0, id2=2^i2+2^i3, id3=2^i3.
//
// R6 design (resubmitted after R7 infra failure): R3 LDG layout (8 lanes/pair,
// one g per block, warp = 4 consecutive b -> data-dependent rows share lines),
// PLUS: each thread loops over NB=4 pairs and register-caches the g-uniform
// row 15, removing 2 of the 8 gather LDG.128 per pair.
// Memory-instr/warp-iter: 11 -> ~9.5.

#define BATCH   1024
#define GROUPS  512
#define NB      4                    // pairs per thread
#define B_TILE  (32 * NB)            // 128 b-values per block (256 threads)

__global__ __launch_bounds__(256, 8)
void hoa_kernel(const float4* __restrict__ Xv,      // [B*G] float4
                const float4* __restrict__ Pv,      // [G*256] float4
                float4* __restrict__ Ov)            // [B*G*16] float4
{
    const int tid = threadIdx.x;
    const int g   = blockIdx.x & (GROUPS - 1);      // block-uniform group
    const int bt  = blockIdx.x >> 9;                // b-tile index (0..7)
    const int q   = tid & 7;                        // float4 chunk 0..7
    const int b0  = bt * B_TILE + (tid >> 3);       // first b for this thread

    // params[g]: [16 rows, 16 float4]; block-uniform base.
    const float4* __restrict__ base = Pv + g * 256;

    // Row 15 is read by every pair (c0 term) and is g-uniform: cache it.
    const float4 p15a = base[15 * 16 + q];
    const float4 p15b = base[15 * 16 + q + 8];

    #pragma unroll
    for (int it = 0; it < NB; ++it) {
        const int b = b0 + it * 32;
        const int p = b * GROUPS + g;

        const float4 x = Xv[p];

        float v0 = x.x, v1 = x.y, v2 = x.z, v3 = x.w;
        int   i0 = 0,   i1 = 1,   i2 = 2,   i3 = 3;

        #define CSWAP(a, bb, ia, ib)                        \
            { bool _sw = (a > bb);                          \
              float _lo = fminf(a, bb), _hi = fmaxf(a, bb); \
              a = _lo; bb = _hi;                            \
              int _t = ia; ia = _sw ? ib : ia; ib = _sw ? _t : ib; }
        CSWAP(v0, v1, i0, i1);
        CSWAP(v2, v3, i2, i3);
        CSWAP(v0, v2, i0, i2);
        CSWAP(v1, v3, i1, i3);
        CSWAP(v1, v2, i1, i2);
        #undef CSWAP

        const float c0 = v0;
        const float c1 = v1 - v0;
        const float c2 = v2 - v1;
        const float c3 = v3 - v2;

        const int e0 = 1 << i0;
        const int e2 = 1 << i2;
        const int e3 = 1 << i3;
        const int id1 = 15 - e0;
        const int id2 = e2 + e3;
        const int id3 = e3;

        const float4* r1 = base + id1 * 16 + q;
        const float4* r2 = base + id2 * 16 + q;
        const float4* r3 = base + id3 * 16 + q;

        const float4 a1 = r1[0], b1 = r1[8];
        const float4 a2 = r2[0], b2 = r2[8];
        const float4 a3 = r3[0], b3 = r3[8];

        float4 oa, ob;
        oa.x = c0 * p15a.x + c1 * a1.x + c2 * a2.x + c3 * a3.x;
        oa.y = c0 * p15a.y + c1 * a1.y + c2 * a2.y + c3 * a3.y;
        oa.z = c0 * p15a.z + c1 * a1.z + c2 * a2.z + c3 * a3.z;
        oa.w = c0 * p15a.w + c1 * a1.w + c2 * a2.w + c3 * a3.w;

        ob.x = c0 * p15b.x + c1 * b1.x + c2 * b2.x + c3 * b3.x;
        ob.y = c0 * p15b.y + c1 * b1.y + c2 * b2.y + c3 * b3.y;
        ob.z = c0 * p15b.z + c1 * b1.z + c2 * b2.z + c3 * b3.z;
        ob.w = c0 * p15b.w + c1 * b1.w + c2 * b2.w + c3 * b3.w;

        float4* __restrict__ o = Ov + (size_t)p * 16 + q;
        o[0] = oa;
        o[8] = ob;
    }
}

extern "C" void kernel_launch(void* const* d_in, const int* in_sizes, int n_in,
                              void* d_out, int out_size)
{
    const float4* Xv = (const float4*)d_in[0];   // X: [1024, 512, 4] f32
    const float4* Pv = (const float4*)d_in[1];   // params: [512, 16, 64] f32
    float4*       Ov = (float4*)d_out;           // out: [1024, 512, 64] f32

    // One block per (g, 128-b tile): 512 * 8 = 4096 blocks, 256 threads.
    const int grid = GROUPS * (BATCH / B_TILE);
    hoa_kernel<<<grid, 256>>>(Xv, Pv, Ov);
}

// round 9
// speedup vs baseline: 1.3773x; 1.0546x over previous
#include <cuda_runtime.h>
#include <cstdint>

// HighOrderActivation: B=1024, G=512, K=4, D=64.
// out[b,g,:] = c0*P[g,15,:] + c1*P[g,id1,:] + c2*P[g,id2,:] + c3*P[g,id3,:]
// (i0..i3)=argsort(X[b,g,:]); c=(min, gaps); id1=15-2^i0, id2=2^i2+2^i3, id3=2^i3.
//
// R9: exact R3 layout (one pair per thread, 8 lanes/pair, one g per block,
// warp = 4 consecutive b for gather line-sharing) — R8's per-thread NB loop
// serialized and regressed, reverted. New: row 15 (g-uniform, read by every
// pair) is staged once in smem; its 2 LDG.128/warp (4cyc L1 data-path each,
// no dedup) become 2 broadcast LDS.128 (conflict-free, dedup to 128B, ~1cyc).

#define BATCH   1024
#define GROUPS  512
#define B_TILE  32
#define PAIRS   (BATCH * GROUPS)

__global__ __launch_bounds__(256, 8)
void hoa_kernel(const float4* __restrict__ Xv,      // [PAIRS] float4
                const float4* __restrict__ Pv,      // [GROUPS*256] float4
                float4* __restrict__ Ov)            // [PAIRS*16] float4
{
    __shared__ float4 sRow15[16];                   // P[g,15,:] = 64 f32

    const int tid = threadIdx.x;
    const int g   = blockIdx.x & (GROUPS - 1);      // block-uniform group
    const int b   = ((blockIdx.x >> 9) << 5) + (tid >> 3);
    const int q   = tid & 7;                        // float4 chunk 0..7

    const int p = b * GROUPS + g;

    // params[g]: [16 rows, 16 float4]; block-uniform base.
    const float4* __restrict__ base = Pv + g * 256;

    // Stage row 15 (one-time, 256B).
    if (tid < 16) sRow15[tid] = base[15 * 16 + tid];

    // X load (independent of smem, overlaps the fill).
    const float4 x = Xv[p];

    float v0 = x.x, v1 = x.y, v2 = x.z, v3 = x.w;
    int   i0 = 0,   i1 = 1,   i2 = 2,   i3 = 3;

    // 5-comparator sorting network, FMNMX + SEL.
    #define CSWAP(a, bb, ia, ib)                        \
        { bool _sw = (a > bb);                          \
          float _lo = fminf(a, bb), _hi = fmaxf(a, bb); \
          a = _lo; bb = _hi;                            \
          int _t = ia; ia = _sw ? ib : ia; ib = _sw ? _t : ib; }
    CSWAP(v0, v1, i0, i1);
    CSWAP(v2, v3, i2, i3);
    CSWAP(v0, v2, i0, i2);
    CSWAP(v1, v3, i1, i3);
    CSWAP(v1, v2, i1, i2);
    #undef CSWAP

    const float c0 = v0;
    const float c1 = v1 - v0;
    const float c2 = v2 - v1;
    const float c3 = v3 - v2;

    const int e0 = 1 << i0;
    const int e2 = 1 << i2;
    const int e3 = 1 << i3;
    const int id1 = 15 - e0;
    const int id2 = e2 + e3;
    const int id3 = e3;

    const float4* r1 = base + id1 * 16 + q;
    const float4* r2 = base + id2 * 16 + q;
    const float4* r3 = base + id3 * 16 + q;

    // Data-dependent gathers stay LDG (line-sharing across the warp's 4 pairs).
    const float4 a1 = r1[0], b1 = r1[8];
    const float4 a2 = r2[0], b2 = r2[8];
    const float4 a3 = r3[0], b3 = r3[8];

    __syncthreads();

    // Row-15 via broadcast LDS (lanes 8-31 duplicate lanes 0-7 -> dedup).
    const float4 a0 = sRow15[q];
    const float4 b0 = sRow15[q + 8];

    float4 oa, ob;
    oa.x = c0 * a0.x + c1 * a1.x + c2 * a2.x + c3 * a3.x;
    oa.y = c0 * a0.y + c1 * a1.y + c2 * a2.y + c3 * a3.y;
    oa.z = c0 * a0.z + c1 * a1.z + c2 * a2.z + c3 * a3.z;
    oa.w = c0 * a0.w + c1 * a1.w + c2 * a2.w + c3 * a3.w;

    ob.x = c0 * b0.x + c1 * b1.x + c2 * b2.x + c3 * b3.x;
    ob.y = c0 * b0.y + c1 * b1.y + c2 * b2.y + c3 * b3.y;
    ob.z = c0 * b0.z + c1 * b1.z + c2 * b2.z + c3 * b3.z;
    ob.w = c0 * b0.w + c1 * b1.w + c2 * b2.w + c3 * b3.w;

    float4* __restrict__ o = Ov + (size_t)p * 16 + q;
    o[0] = oa;
    o[8] = ob;
}

extern "C" void kernel_launch(void* const* d_in, const int* in_sizes, int n_in,
                              void* d_out, int out_size)
{
    const float4* Xv = (const float4*)d_in[0];   // X: [1024, 512, 4] f32
    const float4* Pv = (const float4*)d_in[1];   // params: [512, 16, 64] f32
    float4*       Ov = (float4*)d_out;           // out: [1024, 512, 64] f32

    // One block per (g, 32-b tile): 512 * 32 = 16384 blocks, 256 threads.
    const int grid = GROUPS * (BATCH / B_TILE);
    hoa_kernel<<<grid, 256>>>(Xv, Pv, Ov);
}

// round 10
// speedup vs baseline: 1.3785x; 1.0009x over previous
#include <cuda_runtime.h>
#include <cstdint>

// HighOrderActivation: B=1024, G=512, K=4, D=64.
// out[b,g,:] = c0*P[g,15,:] + c1*P[g,id1,:] + c2*P[g,id2,:] + c3*P[g,id3,:]
// (i0..i3)=argsort(X[b,g,:]); c=(min, gaps); id1=15-2^i0, id2=2^i2+2^i3, id3=2^i3.
//
// R10: R3 layout (8 lanes/pair, one g per block, warp = 4 consecutive b for
// gather line-sharing, full-128B-line loads/stores) with TWO pairs per thread
// (b and b+32) fully unrolled straight-line. Unlike R8's NB loop at 32 regs,
// no occupancy cap: ptxas can interleave the two independent dependency
// chains (ILP-for-occupancy trade). Row 15 loaded once, shared by both pairs:
// 20 mem-instr per warp per 8 pairs (2.5/pair vs R3's 2.75).

#define BATCH   1024
#define GROUPS  512
#define NPAIR   2
#define B_TILE  64          // b-values per block (256 threads, 8 lanes/pair)

__global__ __launch_bounds__(256)
void hoa_kernel(const float4* __restrict__ Xv,      // [B*G] float4
                const float4* __restrict__ Pv,      // [G*256] float4
                float4* __restrict__ Ov)            // [B*G*16] float4
{
    const int tid = threadIdx.x;
    const int g   = blockIdx.x & (GROUPS - 1);      // block-uniform group
    const int bt  = blockIdx.x >> 9;                // b-tile (0..15)
    const int q   = tid & 7;                        // float4 chunk 0..7
    const int b0  = bt * B_TILE + (tid >> 3);       // pair A; pair B = b0+32

    const float4* __restrict__ base = Pv + g * 256;

    // Row 15 (c0 term) is g-uniform: load once, reuse for both pairs.
    const float4 p15a = base[15 * 16 + q];
    const float4 p15b = base[15 * 16 + q + 8];

    float4 oa[NPAIR], ob[NPAIR];
    int    pp[NPAIR];

    #pragma unroll
    for (int u = 0; u < NPAIR; ++u) {
        const int b = b0 + u * 32;
        const int p = b * GROUPS + g;
        pp[u] = p;

        const float4 x = Xv[p];

        float v0 = x.x, v1 = x.y, v2 = x.z, v3 = x.w;
        int   i0 = 0,   i1 = 1,   i2 = 2,   i3 = 3;

        #define CSWAP(a, bb, ia, ib)                        \
            { bool _sw = (a > bb);                          \
              float _lo = fminf(a, bb), _hi = fmaxf(a, bb); \
              a = _lo; bb = _hi;                            \
              int _t = ia; ia = _sw ? ib : ia; ib = _sw ? _t : ib; }
        CSWAP(v0, v1, i0, i1);
        CSWAP(v2, v3, i2, i3);
        CSWAP(v0, v2, i0, i2);
        CSWAP(v1, v3, i1, i3);
        CSWAP(v1, v2, i1, i2);
        #undef CSWAP

        const float c0 = v0;
        const float c1 = v1 - v0;
        const float c2 = v2 - v1;
        const float c3 = v3 - v2;

        const int e0 = 1 << i0;
        const int e2 = 1 << i2;
        const int e3 = 1 << i3;
        const int id1 = 15 - e0;
        const int id2 = e2 + e3;
        const int id3 = e3;

        const float4* r1 = base + id1 * 16 + q;
        const float4* r2 = base + id2 * 16 + q;
        const float4* r3 = base + id3 * 16 + q;

        const float4 a1 = r1[0], b1 = r1[8];
        const float4 a2 = r2[0], b2 = r2[8];
        const float4 a3 = r3[0], b3 = r3[8];

        oa[u].x = c0 * p15a.x + c1 * a1.x + c2 * a2.x + c3 * a3.x;
        oa[u].y = c0 * p15a.y + c1 * a1.y + c2 * a2.y + c3 * a3.y;
        oa[u].z = c0 * p15a.z + c1 * a1.z + c2 * a2.z + c3 * a3.z;
        oa[u].w = c0 * p15a.w + c1 * a1.w + c2 * a2.w + c3 * a3.w;

        ob[u].x = c0 * p15b.x + c1 * b1.x + c2 * b2.x + c3 * b3.x;
        ob[u].y = c0 * p15b.y + c1 * b1.y + c2 * b2.y + c3 * b3.y;
        ob[u].z = c0 * p15b.z + c1 * b1.z + c2 * b2.z + c3 * b3.z;
        ob[u].w = c0 * p15b.w + c1 * b1.w + c2 * b2.w + c3 * b3.w;
    }

    #pragma unroll
    for (int u = 0; u < NPAIR; ++u) {
        float4* __restrict__ o = Ov + (size_t)pp[u] * 16 + q;
        o[0] = oa[u];
        o[8] = ob[u];
    }
}

extern "C" void kernel_launch(void* const* d_in, const int* in_sizes, int n_in,
                              void* d_out, int out_size)
{
    const float4* Xv = (const float4*)d_in[0];   // X: [1024, 512, 4] f32
    const float4* Pv = (const float4*)d_in[1];   // params: [512, 16, 64] f32
    float4*       Ov = (float4*)d_out;           // out: [1024, 512, 64] f32

    // One block per (g, 64-b tile): 512 * 16 = 8192 blocks, 256 threads.
    const int grid = GROUPS * (BATCH / B_TILE);
    hoa_kernel<<<grid, 256>>>(Xv, Pv, Ov);
}

// round 13
// speedup vs baseline: 1.4476x; 1.0501x over previous
#include <cuda_runtime.h>
#include <cstdint>

// HighOrderActivation: B=1024, G=512, K=4, D=64.
// out[b,g,:] = c0*P[g,15,:] + c1*P[g,id1,:] + c2*P[g,id2,:] + c3*P[g,id3,:]
// (i0..i3)=argsort(X[b,g,:]); c=(min, gaps); id1=15-2^i0, id2=2^i2+2^i3, id3=2^i3.
//
// R12 = R11 design, macro replaced by __forceinline__ function (the macro
// broke the harness compile). R3 layout (8 lanes/pair, one g per block,
// warp = 4 consecutive b for gather line-sharing, full-128B-line accesses).
// Each thread processes TWO pairs SEQUENTIALLY (b, b+32) with both X loads
// hoisted: X is the only DRAM-latency load and R3 exposed it (L1 74% busy /
// 26% starved). Gathers not interleaved across pairs (R10's occupancy
// mistake); occupancy held at 6 blocks/SM.

#define BATCH   1024
#define GROUPS  512
#define B_TILE  64          // 2 pairs per thread, 256 threads, 8 lanes/pair

__device__ __forceinline__ void process_pair(
    const float4 x, int p, const float4* __restrict__ base, int q,
    float4* __restrict__ Ov)
{
    float v0 = x.x, v1 = x.y, v2 = x.z, v3 = x.w;
    int   i0 = 0,   i1 = 1,   i2 = 2,   i3 = 3;

    // 5-comparator sorting network, FMNMX + SEL.
    {
        bool sw;
        float lo, hi;
        int t;
        sw = v0 > v1; lo = fminf(v0, v1); hi = fmaxf(v0, v1); v0 = lo; v1 = hi;
        t = i0; i0 = sw ? i1 : i0; i1 = sw ? t : i1;
        sw = v2 > v3; lo = fminf(v2, v3); hi = fmaxf(v2, v3); v2 = lo; v3 = hi;
        t = i2; i2 = sw ? i3 : i2; i3 = sw ? t : i3;
        sw = v0 > v2; lo = fminf(v0, v2); hi = fmaxf(v0, v2); v0 = lo; v2 = hi;
        t = i0; i0 = sw ? i2 : i0; i2 = sw ? t : i2;
        sw = v1 > v3; lo = fminf(v1, v3); hi = fmaxf(v1, v3); v1 = lo; v3 = hi;
        t = i1; i1 = sw ? i3 : i1; i3 = sw ? t : i3;
        sw = v1 > v2; lo = fminf(v1, v2); hi = fmaxf(v1, v2); v1 = lo; v2 = hi;
        t = i1; i1 = sw ? i2 : i1; i2 = sw ? t : i2;
    }

    const float c0 = v0;
    const float c1 = v1 - v0;
    const float c2 = v2 - v1;
    const float c3 = v3 - v2;

    const int e0 = 1 << i0;
    const int e2 = 1 << i2;
    const int e3 = 1 << i3;
    const int id1 = 15 - e0;
    const int id2 = e2 + e3;
    const int id3 = e3;

    const float4* r0 = base + 15  * 16 + q;
    const float4* r1 = base + id1 * 16 + q;
    const float4* r2 = base + id2 * 16 + q;
    const float4* r3 = base + id3 * 16 + q;

    const float4 a0 = r0[0], bb0 = r0[8];
    const float4 a1 = r1[0], bb1 = r1[8];
    const float4 a2 = r2[0], bb2 = r2[8];
    const float4 a3 = r3[0], bb3 = r3[8];

    float4 oa, ob;
    oa.x = c0 * a0.x + c1 * a1.x + c2 * a2.x + c3 * a3.x;
    oa.y = c0 * a0.y + c1 * a1.y + c2 * a2.y + c3 * a3.y;
    oa.z = c0 * a0.z + c1 * a1.z + c2 * a2.z + c3 * a3.z;
    oa.w = c0 * a0.w + c1 * a1.w + c2 * a2.w + c3 * a3.w;

    ob.x = c0 * bb0.x + c1 * bb1.x + c2 * bb2.x + c3 * bb3.x;
    ob.y = c0 * bb0.y + c1 * bb1.y + c2 * bb2.y + c3 * bb3.y;
    ob.z = c0 * bb0.z + c1 * bb1.z + c2 * bb2.z + c3 * bb3.z;
    ob.w = c0 * bb0.w + c1 * bb1.w + c2 * bb2.w + c3 * bb3.w;

    float4* __restrict__ o = Ov + (size_t)p * 16 + q;
    o[0] = oa;
    o[8] = ob;
}

__global__ __launch_bounds__(256, 6)
void hoa_kernel(const float4* __restrict__ Xv,      // [B*G] float4
                const float4* __restrict__ Pv,      // [G*256] float4
                float4* __restrict__ Ov)            // [B*G*16] float4
{
    const int tid = threadIdx.x;
    const int g   = blockIdx.x & (GROUPS - 1);      // block-uniform group
    const int bt  = blockIdx.x >> 9;                // b-tile (0..15)
    const int q   = tid & 7;                        // float4 chunk 0..7
    const int b0  = bt * B_TILE + (tid >> 3);       // pair A; pair B = b0+32

    const int p0 = b0 * GROUPS + g;
    const int p1 = (b0 + 32) * GROUPS + g;

    // Hoist BOTH DRAM-latency X loads before any dependent work.
    const float4 x0 = Xv[p0];
    const float4 x1 = Xv[p1];

    const float4* __restrict__ base = Pv + g * 256;

    process_pair(x0, p0, base, q, Ov);
    process_pair(x1, p1, base, q, Ov);
}

extern "C" void kernel_launch(void* const* d_in, const int* in_sizes, int n_in,
                              void* d_out, int out_size)
{
    const float4* Xv = (const float4*)d_in[0];   // X: [1024, 512, 4] f32
    const float4* Pv = (const float4*)d_in[1];   // params: [512, 16, 64] f32
    float4*       Ov = (float4*)d_out;           // out: [1024, 512, 64] f32

    // One block per (g, 64-b tile): 512 * 16 = 8192 blocks, 256 threads.
    const int grid = GROUPS * (BATCH / B_TILE);
    hoa_kernel<<<grid, 256>>>(Xv, Pv, Ov);
}